// round 4
// baseline (speedup 1.0000x reference)
#include <cuda_runtime.h>
#include <cuda_bf16.h>

#define WG_EPS 1e-8f

__global__ __launch_bounds__(256) void wasserstein_gaussian_kernel(
    const float* __restrict__ loc1,
    const float* __restrict__ scale1,
    const float* __restrict__ rot1,
    const float* __restrict__ loc2,
    const float* __restrict__ scale2,
    const float* __restrict__ rot2,
    float* __restrict__ out,
    int B)
{
    int b = blockIdx.x * blockDim.x + threadIdx.x;
    if (b >= B) return;

    // ---- loads (warp-contiguous, fully coalesced at sector level) ----
    float l1[3], l2[3], s1[3], s2[3], r1[9], r2[9];
#pragma unroll
    for (int i = 0; i < 3; i++) {
        l1[i] = loc1[3 * b + i];
        l2[i] = loc2[3 * b + i];
        s1[i] = fmaxf(scale1[3 * b + i], WG_EPS);
        s2[i] = fmaxf(scale2[3 * b + i], WG_EPS);
    }
#pragma unroll
    for (int i = 0; i < 9; i++) {
        r1[i] = rot1[9 * b + i];
        r2[i] = rot2[9 * b + i];
    }

    // ---- loc term ----
    float d0 = l1[0] - l2[0], d1 = l1[1] - l2[1], d2 = l1[2] - l2[2];
    float loc_diff2 = d0 * d0 + d1 * d1 + d2 * d2;

    // ---- cov2 = R2 diag(s2) R2^T  (symmetric, 6 unique entries stored full) ----
    float cov2[3][3];
#pragma unroll
    for (int i = 0; i < 3; i++) {
#pragma unroll
        for (int k = i; k < 3; k++) {
            float v = r2[3 * i + 0] * s2[0] * r2[3 * k + 0]
                    + r2[3 * i + 1] * s2[1] * r2[3 * k + 1]
                    + r2[3 * i + 2] * s2[2] * r2[3 * k + 2];
            cov2[i][k] = v;
            cov2[k][i] = v;
        }
    }
    float tr_cov2 = cov2[0][0] + cov2[1][1] + cov2[2][2];

    // ---- M = R1^T cov2 R1 ----
    float T[3][3];
#pragma unroll
    for (int j = 0; j < 3; j++)
#pragma unroll
        for (int l = 0; l < 3; l++)
            T[j][l] = cov2[j][0] * r1[0 * 3 + l]
                    + cov2[j][1] * r1[1 * 3 + l]
                    + cov2[j][2] * r1[2 * 3 + l];

    float M[3][3];
#pragma unroll
    for (int i = 0; i < 3; i++)
#pragma unroll
        for (int l = 0; l < 3; l++)
            M[i][l] = r1[0 * 3 + i] * T[0][l]
                    + r1[1 * 3 + i] * T[1][l]
                    + r1[2 * 3 + i] * T[2][l];

    // ---- E = diag(sqrt(s1)) M diag(sqrt(s1)), symmetrized + EPS*I ----
    float q0 = sqrtf(s1[0]), q1 = sqrtf(s1[1]), q2 = sqrtf(s1[2]);
    float a00 = s1[0] * M[0][0] + WG_EPS;
    float a11 = s1[1] * M[1][1] + WG_EPS;
    float a22 = s1[2] * M[2][2] + WG_EPS;
    float a01 = q0 * q1 * 0.5f * (M[0][1] + M[1][0]);
    float a02 = q0 * q2 * 0.5f * (M[0][2] + M[2][0]);
    float a12 = q1 * q2 * 0.5f * (M[1][2] + M[2][1]);

    // ---- eigenvalues of symmetric 3x3 (trigonometric / Smith method) ----
    float q = (a00 + a11 + a22) * (1.0f / 3.0f);
    float p1 = a01 * a01 + a02 * a02 + a12 * a12;
    float m0 = a00 - q, m1 = a11 - q, m2 = a22 - q;
    float p2 = m0 * m0 + m1 * m1 + m2 * m2 + 2.0f * p1;

    float sum_sqrt;
    if (p2 <= 1e-24f) {
        // (near-)scalar matrix: all eigenvalues = q
        sum_sqrt = 3.0f * sqrtf(fmaxf(q, WG_EPS));
    } else {
        float p  = sqrtf(p2 * (1.0f / 6.0f));
        float ip = 1.0f / p;
        float b00 = m0 * ip, b11 = m1 * ip, b22 = m2 * ip;
        float b01 = a01 * ip, b02 = a02 * ip, b12 = a12 * ip;
        float detB = b00 * (b11 * b22 - b12 * b12)
                   - b01 * (b01 * b22 - b12 * b02)
                   + b02 * (b01 * b12 - b11 * b02);
        float r = fminf(fmaxf(0.5f * detB, -1.0f), 1.0f);
        float phi = acosf(r) * (1.0f / 3.0f);
        float tp = 2.0f * p;
        float e1 = q + tp * cosf(phi);                       // largest
        float e3 = q + tp * cosf(phi + 2.0943951023931953f); // smallest
        float e2 = 3.0f * q - e1 - e3;
        sum_sqrt = sqrtf(fmaxf(e1, WG_EPS))
                 + sqrtf(fmaxf(e2, WG_EPS))
                 + sqrtf(fmaxf(e3, WG_EPS));
    }

    // ---- assemble W2 ----
    float cov_w = (s1[0] + s1[1] + s1[2]) + tr_cov2 - 2.0f * sum_sqrt;
    cov_w = fmaxf(cov_w, 0.0f);
    out[b] = sqrtf(fmaxf(loc_diff2 + cov_w, WG_EPS));
}

extern "C" void kernel_launch(void* const* d_in, const int* in_sizes, int n_in,
                              void* d_out, int out_size)
{
    const float* loc1   = (const float*)d_in[0];
    const float* scale1 = (const float*)d_in[1];
    const float* rot1   = (const float*)d_in[2];
    const float* loc2   = (const float*)d_in[3];
    const float* scale2 = (const float*)d_in[4];
    const float* rot2   = (const float*)d_in[5];
    float* out = (float*)d_out;

    int B = in_sizes[0] / 3;
    int threads = 256;
    int blocks = (B + threads - 1) / threads;
    wasserstein_gaussian_kernel<<<blocks, threads>>>(
        loc1, scale1, rot1, loc2, scale2, rot2, out, B);
}